// round 16
// baseline (speedup 1.0000x reference)
#include <cuda_runtime.h>
#include <cuda_fp16.h>
#include <cstdint>

#define BB 64
#define SS 196
#define HALFS 98
#define OO 10
#define ESLAB_U2 2048          // uint2 per E-slab: [mm 0..31][n 0..63]
#define ESLAB_B 16384          // bytes per E-slab
#define RING 6
#define NT 160                 // 4 worker warps + 1 TMA warp

// E = C - I in fp16, chain-ordered. uint2 = {half2 @ m=2mm, half2 @ m=2mm+1}
__device__ __align__(128) uint2 g_EhL[HALFS * ESLAB_U2];
__device__ __align__(128) uint2 g_EhR[HALFS * ESLAB_U2];   // transposed
__device__ float g_vecL[BB][64];
__device__ unsigned int g_flag[BB];

// ---------------------------------------------------------------------------
__device__ __forceinline__ uint32_t smem_u32(const void* p) {
    uint32_t a;
    asm("{ .reg .u64 t; cvta.to.shared.u64 t, %1; cvt.u32.u64 %0, t; }"
        : "=r"(a) : "l"(p));
    return a;
}
__device__ __forceinline__ void mbar_init(uint32_t a, uint32_t cnt) {
    asm volatile("mbarrier.init.shared.b64 [%0], %1;" :: "r"(a), "r"(cnt) : "memory");
}
__device__ __forceinline__ void mbar_expect_tx(uint32_t a, uint32_t bytes) {
    asm volatile("mbarrier.arrive.expect_tx.shared.b64 _, [%0], %1;"
                 :: "r"(a), "r"(bytes) : "memory");
}
__device__ __forceinline__ void mbar_wait(uint32_t a, uint32_t phase) {
    asm volatile(
        "{\n\t.reg .pred P;\n\t"
        "W_%=:\n\t"
        "mbarrier.try_wait.parity.shared.b64 P, [%0], %1;\n\t"
        "@!P bra W_%=;\n\t}"
        :: "r"(a), "r"(phase) : "memory");
}
__device__ __forceinline__ void bulk_g2s(uint32_t dst, const void* src,
                                         uint32_t bytes, uint32_t mbar) {
    asm volatile(
        "cp.async.bulk.shared::cluster.global.mbarrier::complete_tx::bytes "
        "[%0], [%1], %2, [%3];"
        :: "r"(dst), "l"(src), "r"(bytes), "r"(mbar) : "memory");
}

__device__ __forceinline__ uint32_t pack_e(float2 a) {
    __half2 h = __float22half2_rn(a);
    uint32_t u;
    memcpy(&u, &h, 4);
    return u;
}

// ---------------------------------------------------------------------------
// Kernel 1: merged prep. bid < 98 -> EhL[bid] (direct); else EhR[bid-98]
// (transpose via SMEM tile). Also re-zeros the inter-CTA flags each replay.
// ---------------------------------------------------------------------------
__global__ __launch_bounds__(256) void prep_kernel(const float* __restrict__ cores)
{
    __shared__ uint2 tile[32][65];
    const int bid = blockIdx.x;
    const int t = threadIdx.x;

    if (bid == 0 && t < BB) g_flag[t] = 0u;

    if (bid < HALFS) {
        const float2* c2 = (const float2*)cores + (size_t)bid * 4096;
        uint2* dst = g_EhL + (size_t)bid * ESLAB_U2;
#pragma unroll
        for (int i = 0; i < 8; i++) {
            int idx = t + i * 256;
            int mm = idx >> 6, n = idx & 63;
            float2 a = c2[(2 * mm) * 64 + n];
            float2 b = c2[(2 * mm + 1) * 64 + n];
            if (2 * mm == n)     { a.x -= 1.f; a.y -= 1.f; }
            if (2 * mm + 1 == n) { b.x -= 1.f; b.y -= 1.f; }
            dst[idx] = make_uint2(pack_e(a), pack_e(b));
        }
    } else {
        const int k = bid - HALFS;
        const int s = SS - 1 - k;
        const float4* c4 = (const float4*)cores + (size_t)s * 2048;  // [n][mm]
        uint2* dst = g_EhR + (size_t)k * ESLAB_U2;
#pragma unroll
        for (int i = 0; i < 8; i++) {
            int idx = t + i * 256;                 // mm fastest -> coalesced
            int n = idx >> 5, mm = idx & 31;
            float4 f = c4[idx];
            float2 a = make_float2(f.x, f.y);
            float2 b = make_float2(f.z, f.w);
            if (2 * mm == n)     { a.x -= 1.f; a.y -= 1.f; }
            if (2 * mm + 1 == n) { b.x -= 1.f; b.y -= 1.f; }
            tile[mm][n] = make_uint2(pack_e(a), pack_e(b));
        }
        __syncthreads();
#pragma unroll
        for (int i = 0; i < 8; i++) {
            int idx = t + i * 256;                 // n fastest -> coalesced
            int mm = idx >> 6, n = idx & 63;
            dst[idx] = tile[mm][n];
        }
    }
}

// ---------------------------------------------------------------------------
// Kernel 2: 128 CTAs x 160 threads — ONE chain per CTA (batch b, half).
// Chain loop identical to R15. Fused epilogue:
//   CTA (0,b): publish vecL[b] + release flag, exit.
//   CTA (1,b): keep vecR in smem, acquire-spin on flag, 5 warps compute
//              out[b][0..9] (warp = 2 o's, 32 LDG.128/lane, oc L2-resident).
// Safe: all 128 CTAs co-resident (<=148 SMs), one-way dependency only.
// ---------------------------------------------------------------------------
__global__ __launch_bounds__(NT, 1) void chain_kernel(const float* __restrict__ x,
                                                      const float* __restrict__ oc,
                                                      float* __restrict__ out)
{
    extern __shared__ __align__(128) unsigned char dynsm[];
    uint2*  ringE = (uint2*)dynsm;                                // 6 x 16KB
    float*  lvsm  = (float*)(dynsm + RING * ESLAB_B);             // [2][72]
    float2* xsh   = (float2*)(dynsm + RING * ESLAB_B + 576);      // [98]
    uint64_t* mbp = (uint64_t*)(dynsm + RING * ESLAB_B + 576 + 784);
    __shared__ float Ls[64];
    __shared__ float Rs[64];

    const uint32_t fb = smem_u32(mbp);
    const uint32_t ru = smem_u32(dynsm);

    const int t    = threadIdx.x;
    const int w    = t >> 5;
    const int lane = t & 31;
    const int g    = lane >> 4;
    const int half = blockIdx.x >> 6;
    const int b    = blockIdx.x & 63;

    const uint2* srcE = half ? g_EhR : g_EhL;     // both chain-ordered

    // stage x in iteration order
    const float2* xf = (const float2*)x;          // [B][S]
    for (int k = t; k < HALFS; k += NT) {
        int s = half ? (SS - 1 - k) : k;
        xsh[k] = xf[b * SS + s];
    }
    // init lv buf0 (padded layout: half h at offset h*36)
    if (t < 64) {
        int h = t >> 5, p = t & 31;
        lvsm[h * 36 + p] = (t == 0) ? 1.f : 0.f;
    }
    if (t == 0)
        for (int j = 0; j < RING; j++) mbar_init(fb + 8 * j, 1);
    __syncthreads();

    if (w == 4 && lane == 0) {            // prologue: slabs 0..5
        for (int s = 0; s < RING; s++) {
            mbar_expect_tx(fb + 8 * s, ESLAB_B);
            bulk_g2s(ru + s * ESLAB_B, srcE + (size_t)s * ESLAB_U2,
                     ESLAB_B, fb + 8 * s);
        }
        mbar_wait(fb + 0, 0);             // slab 0 (reg load)
        mbar_wait(fb + 8, 0);             // slab 1 (step-0 prefetch)
    }
    __syncthreads();

    if (w < 4) {
        // ============================ workers ============================
        const int c  = lane & 15;
        const int n  = w * 16 + c;
        const int eoff = g * 1024 + n;    // uint2 offset of (mm = g*16, n)
        const int hh = w >> 1;            // n >> 5
        const int sto = hh * 36 + (w & 1) * 16 + c;   // lv slot for column n
        const bool wr = (g == 0);

        float2 A[32], B[32];
        {
            const uint2* P = ringE + eoff;
#pragma unroll
            for (int j = 0; j < 16; j++) {
                uint2 e = P[j * 64];
                A[2 * j]     = __half22float2(*reinterpret_cast<const __half2*>(&e.x));
                A[2 * j + 1] = __half22float2(*reinterpret_cast<const __half2*>(&e.y));
            }
        }
        int slotn = 1;                    // ring slot of slab k+1

#define WSTEP(CUR, NXT, K, PAR)                                              \
        {                                                                    \
            float2 xk = xsh[(K)];                                            \
            float p0;                                                        \
            {                                                                \
                const float4* lv4 = (const float4*)(lvsm + (PAR) * 72 + g * 36); \
                float4 L[8];                                                 \
                _Pragma("unroll")                                            \
                for (int q = 0; q < 8; q++) L[q] = lv4[q];                   \
                float sx0 = 0.f, sx1 = 0.f, sy0 = 0.f, sy1 = 0.f;            \
                _Pragma("unroll")                                            \
                for (int q = 0; q < 8; q++) {                                \
                    float2 c0 = CUR[4*q+0], c1 = CUR[4*q+1];                 \
                    float2 c2 = CUR[4*q+2], c3 = CUR[4*q+3];                 \
                    sx0 = fmaf(L[q].x, c0.x, sx0); sy0 = fmaf(L[q].x, c0.y, sy0); \
                    sx1 = fmaf(L[q].y, c1.x, sx1); sy1 = fmaf(L[q].y, c1.y, sy1); \
                    sx0 = fmaf(L[q].z, c2.x, sx0); sy0 = fmaf(L[q].z, c2.y, sy0); \
                    sx1 = fmaf(L[q].w, c3.x, sx1); sy1 = fmaf(L[q].w, c3.y, sy1); \
                }                                                            \
                p0 = fmaf(xk.x, sx0 + sx1, xk.y * (sy0 + sy1));              \
            }                                                                \
            float lvo = 0.f;                                                 \
            if (wr) lvo = lvsm[(PAR) * 72 + sto];                            \
            float oth = __shfl_xor_sync(0xffffffffu, p0, 16);                \
            if (wr) lvsm[((PAR) ^ 1) * 72 + sto] =                           \
                fmaf(xk.x + xk.y, lvo, p0 + oth);                            \
            if ((K) < HALFS - 1) {                                           \
                const uint2* Ns = ringE + slotn * ESLAB_U2 + eoff;           \
                _Pragma("unroll")                                            \
                for (int j = 0; j < 16; j++) {                               \
                    uint2 e = Ns[j * 64];                                    \
                    NXT[2 * j] =                                             \
                        __half22float2(*reinterpret_cast<const __half2*>(&e.x)); \
                    NXT[2 * j + 1] =                                         \
                        __half22float2(*reinterpret_cast<const __half2*>(&e.y)); \
                }                                                            \
            }                                                                \
            slotn = (slotn == RING - 1) ? 0 : slotn + 1;                     \
            __syncthreads();                                                 \
        }

#pragma unroll 1
        for (int k = 0; k < HALFS; k += 2) {
            WSTEP(A, B, k, 0);
            WSTEP(B, A, k + 1, 1);
        }
#undef WSTEP
    } else {
        // ============================ TMA warp ============================
#pragma unroll 1
        for (int k = 0; k < HALFS; k++) {
            if (lane == 0 && k + 2 < HALFS)     // certify slab k+2
                mbar_wait(fb + 8 * ((k + 2) % RING), ((k + 2) / RING) & 1);
            __syncthreads();
            if (lane == 0 && k + RING < HALFS) {   // refill slot k%RING
                mbar_expect_tx(fb + 8 * (k % RING), ESLAB_B);
                bulk_g2s(ru + (k % RING) * ESLAB_B,
                         srcE + (size_t)(k + RING) * ESLAB_U2,
                         ESLAB_B, fb + 8 * (k % RING));
            }
        }
    }

    // ======================== fused epilogue ========================
    // final lv is in buffer 0 (98 steps, even)
    if (half == 0) {
        if (t < 64) {
            int h = t >> 5, p = t & 31;
            g_vecL[b][t] = lvsm[h * 36 + p];
        }
        __threadfence();
        __syncthreads();
        if (t == 0) atomicExch(&g_flag[b], 1u);     // release
    } else {
        if (t < 64) {
            int h = t >> 5, p = t & 31;
            Rs[t] = lvsm[h * 36 + p];
        }
        if (t == 0) {                               // acquire
            while (atomicAdd(&g_flag[b], 0u) == 0u) { }
            __threadfence();
        }
        __syncthreads();
        if (t < 64) Ls[t] = g_vecL[b][t];
        __syncthreads();

        // 5 warps x 2 outputs: out[b][o] = sum L[l] * oc[o][l][r] * R[r]
#pragma unroll
        for (int oo = 0; oo < 2; oo++) {
            const int o = w * 2 + oo;
            const float4* oc4 = (const float4*)oc + o * 1024;
            float acc = 0.f;
#pragma unroll
            for (int j = 0; j < 32; j++) {
                int idx = lane + 32 * j;
                float4 a = oc4[idx];
                const float4 r = *(const float4*)(Rs + (idx & 15) * 4);
                float d = fmaf(a.x, r.x, fmaf(a.y, r.y, fmaf(a.z, r.z, a.w * r.w)));
                acc = fmaf(Ls[idx >> 4], d, acc);
            }
#pragma unroll
            for (int off = 16; off; off >>= 1)
                acc += __shfl_down_sync(0xffffffffu, acc, off);
            if (lane == 0) out[b * OO + o] = acc;
        }
    }
}

// ---------------------------------------------------------------------------
extern "C" void kernel_launch(void* const* d_in, const int* in_sizes, int n_in,
                              void* d_out, int out_size)
{
    const float* x = nullptr;
    const float* cores = nullptr;
    const float* oc = nullptr;
    for (int i = 0; i < n_in; i++) {
        if (in_sizes[i] == BB * SS * 2)              x = (const float*)d_in[i];
        else if (in_sizes[i] == SS * 64 * 64 * 2)    cores = (const float*)d_in[i];
        else if (in_sizes[i] == OO * 64 * 64)        oc = (const float*)d_in[i];
    }

    const int DYN_SMEM = RING * ESLAB_B + 576 + 784 + 64;
    cudaFuncSetAttribute(chain_kernel, cudaFuncAttributeMaxDynamicSharedMemorySize, DYN_SMEM);

    prep_kernel<<<SS, 256>>>(cores);
    chain_kernel<<<128, NT, DYN_SMEM>>>(x, oc, (float*)d_out);
}